// round 5
// baseline (speedup 1.0000x reference)
#include <cuda_runtime.h>
#include <cuda_bf16.h>
#include <cstdint>

// ---------------- problem constants ----------------
#define D_MODEL   512
#define N_LAYERS  4
#define D_STATE   16
#define D_CONV    4
#define D_INNER   1024
#define DT_RANK   32
#define BATCH     4
#define SEQ       1024
#define M_TOK     (BATCH * SEQ)          // 4096 tokens

// ---------------- scratch (device globals; no cudaMalloc allowed) ----------------
__device__ float g_xn [M_TOK * D_MODEL];      // layernorm output
__device__ float g_xz [M_TOK * 2 * D_INNER];  // in_proj output (xc_pre | z)
__device__ float g_xc [M_TOK * D_INNER];      // conv+silu output
__device__ float g_dbl[M_TOK * 64];           // x_proj output (dtr|B|C)
__device__ float g_dt [M_TOK * D_INNER];      // softplus dt
__device__ float g_y  [M_TOK * D_INNER];      // scan output (pre out_proj)

// ---------------- layernorm: one warp per row of 512 ----------------
__global__ __launch_bounds__(256) void ln_kernel(
    const float* __restrict__ x, const float* __restrict__ g,
    const float* __restrict__ b, float* __restrict__ out)
{
    int warp = (blockIdx.x * blockDim.x + threadIdx.x) >> 5;
    int lane = threadIdx.x & 31;
    const float4* xr = (const float4*)(x + (size_t)warp * D_MODEL);
    float4 v[4];
    float s = 0.f;
    #pragma unroll
    for (int i = 0; i < 4; i++) {
        v[i] = __ldg(xr + lane + 32 * i);
        s += v[i].x + v[i].y + v[i].z + v[i].w;
    }
    #pragma unroll
    for (int o = 16; o; o >>= 1) s += __shfl_xor_sync(0xffffffffu, s, o);
    float mean = s * (1.0f / D_MODEL);
    float vs = 0.f;
    #pragma unroll
    for (int i = 0; i < 4; i++) {
        float dx;
        dx = v[i].x - mean; vs += dx * dx;
        dx = v[i].y - mean; vs += dx * dx;
        dx = v[i].z - mean; vs += dx * dx;
        dx = v[i].w - mean; vs += dx * dx;
    }
    #pragma unroll
    for (int o = 16; o; o >>= 1) vs += __shfl_xor_sync(0xffffffffu, vs, o);
    float inv = rsqrtf(vs * (1.0f / D_MODEL) + 1e-5f);

    const float4* g4 = (const float4*)g;
    const float4* b4 = (const float4*)b;
    float4* o4 = (float4*)(out + (size_t)warp * D_MODEL);
    #pragma unroll
    for (int i = 0; i < 4; i++) {
        int idx = lane + 32 * i;
        float4 gv = __ldg(g4 + idx), bv = __ldg(b4 + idx), r;
        r.x = (v[i].x - mean) * inv * gv.x + bv.x;
        r.y = (v[i].y - mean) * inv * gv.y + bv.y;
        r.z = (v[i].z - mean) * inv * gv.z + bv.z;
        r.w = (v[i].w - mean) * inv * gv.w + bv.w;
        o4[idx] = r;
    }
}

// ---------------- generic tiled GEMM: C[M,N] = A[M,K] * W[N,K]^T ----------------
// EPI: 0 = store, 1 = softplus(acc + bias[n]), 2 = accumulate into C
template<int BM, int BN, int BK, int TM, int TN, int EPI>
__global__ __launch_bounds__(256) void gemm_kernel(
    const float* __restrict__ A, int lda,
    const float* __restrict__ W, int ldb,
    float* __restrict__ C, int ldc,
    int M, int N, int K,
    const float* __restrict__ bias)
{
    __shared__ float As[BK][BM + 4];
    __shared__ float Ws[BK][BN + 4];

    const int tid = threadIdx.x;
    const int m0 = blockIdx.y * BM;
    const int n0 = blockIdx.x * BN;
    constexpr int NTX = BN / TN;
    const int tx = tid % NTX;
    const int ty = tid / NTX;

    float acc[TM][TN];
    #pragma unroll
    for (int i = 0; i < TM; i++)
        #pragma unroll
        for (int j = 0; j < TN; j++) acc[i][j] = 0.f;

    for (int k0 = 0; k0 < K; k0 += BK) {
        // load A tile (BM x BK); all dims divide evenly, no guards needed
        #pragma unroll
        for (int i = tid; i < BM * BK; i += 256) {
            int m = i / BK, k = i % BK;
            As[k][m] = __ldg(A + (size_t)(m0 + m) * lda + k0 + k);
        }
        // load W tile (BN x BK)
        #pragma unroll
        for (int i = tid; i < BN * BK; i += 256) {
            int n = i / BK, k = i % BK;
            Ws[k][n] = __ldg(W + (size_t)(n0 + n) * ldb + k0 + k);
        }
        __syncthreads();
        #pragma unroll
        for (int k = 0; k < BK; ++k) {
            float a[TM], bb[TN];
            #pragma unroll
            for (int i = 0; i < TM; i++) a[i] = As[k][ty * TM + i];
            #pragma unroll
            for (int j = 0; j < TN; j++) bb[j] = Ws[k][tx * TN + j];
            #pragma unroll
            for (int i = 0; i < TM; i++)
                #pragma unroll
                for (int j = 0; j < TN; j++)
                    acc[i][j] = fmaf(a[i], bb[j], acc[i][j]);
        }
        __syncthreads();
    }

    #pragma unroll
    for (int i = 0; i < TM; i++) {
        int m = m0 + ty * TM + i;
        #pragma unroll
        for (int j = 0; j < TN; j++) {
            int n = n0 + tx * TN + j;
            float v = acc[i][j];
            if (EPI == 1) {
                v += __ldg(bias + n);
                // stable softplus
                v = fmaxf(v, 0.f) + log1pf(expf(-fabsf(v)));
            } else if (EPI == 2) {
                v += C[(size_t)m * ldc + n];
            }
            C[(size_t)m * ldc + n] = v;
        }
    }
}

// ---------------- causal depthwise conv (k=4) + bias + silu ----------------
__global__ __launch_bounds__(256) void conv_silu_kernel(
    const float* __restrict__ xz, const float* __restrict__ cw,
    const float* __restrict__ cb, float* __restrict__ xc)
{
    int idx = blockIdx.x * blockDim.x + threadIdx.x;   // over 4096*1024
    int d  = idx & (D_INNER - 1);
    int tk = idx >> 10;           // token
    int l  = tk & (SEQ - 1);
    int b  = tk >> 10;

    float4 w = __ldg((const float4*)cw + d);
    float acc = __ldg(cb + d);
    const float* base = xz + ((size_t)(b << 10)) * (2 * D_INNER) + d;
    #pragma unroll
    for (int k = 0; k < D_CONV; k++) {
        int lk = l - (D_CONV - 1) + k;
        if (lk >= 0) {
            float xv = __ldg(base + (size_t)lk * (2 * D_INNER));
            float wk = (k == 0) ? w.x : (k == 1) ? w.y : (k == 2) ? w.z : w.w;
            acc = fmaf(wk, xv, acc);
        }
    }
    // silu
    float sg = 1.f / (1.f + __expf(-acc));
    xc[idx] = acc * sg;
}

// ---------------- selective scan: 4 threads per channel (4 states each) ----------------
// fuses: h = exp(dt*A)*h + dt*B*x ; y = h.C ; y = (y + Dp*x) * silu(z)
__global__ __launch_bounds__(256) void scan_kernel(
    const float* __restrict__ dt, const float* __restrict__ dbl,
    const float* __restrict__ xc, const float* __restrict__ xz,
    const float* __restrict__ A_log, const float* __restrict__ Dp,
    float* __restrict__ y)
{
    int tid = blockIdx.x * blockDim.x + threadIdx.x;   // 16384 threads
    int sub = tid & 3;
    int ch  = tid >> 2;                 // 0..4095
    int d   = ch & (D_INNER - 1);
    int b   = ch >> 10;

    float A0 = -__expf(__ldg(A_log + d * D_STATE + sub * 4 + 0));
    float A1 = -__expf(__ldg(A_log + d * D_STATE + sub * 4 + 1));
    float A2 = -__expf(__ldg(A_log + d * D_STATE + sub * 4 + 2));
    float A3 = -__expf(__ldg(A_log + d * D_STATE + sub * 4 + 3));
    float Dv = __ldg(Dp + d);

    float h0 = 0.f, h1 = 0.f, h2 = 0.f, h3 = 0.f;

    const size_t tk0 = (size_t)(b << 10);
    const float* dtp = dt  + tk0 * D_INNER + d;
    const float* xcp = xc  + tk0 * D_INNER + d;
    const float* zp  = xz  + tk0 * (2 * D_INNER) + D_INNER + d;
    const float* blp = dbl + tk0 * 64 + DT_RANK + sub * 4;   // B at +0, C at +16
    float* yp = y + tk0 * D_INNER + d;

    // register prefetch, depth 4
    const int PF = 4;
    float  dtb[PF], xvb[PF], zvb[PF];
    float4 Bb[PF], Cb[PF];
    #pragma unroll
    for (int i = 0; i < PF; i++) {
        dtb[i] = __ldg(dtp + (size_t)i * D_INNER);
        xvb[i] = __ldg(xcp + (size_t)i * D_INNER);
        zvb[i] = __ldg(zp  + (size_t)i * (2 * D_INNER));
        Bb[i]  = *(const float4*)(blp + (size_t)i * 64);
        Cb[i]  = *(const float4*)(blp + (size_t)i * 64 + D_STATE);
    }

    #pragma unroll 4
    for (int l = 0; l < SEQ; ++l) {
        int s = l & (PF - 1);
        float  dtv = dtb[s], xv = xvb[s], zv = zvb[s];
        float4 Bv = Bb[s], Cv = Cb[s];
        int lp = l + PF;
        if (lp < SEQ) {
            dtb[s] = __ldg(dtp + (size_t)lp * D_INNER);
            xvb[s] = __ldg(xcp + (size_t)lp * D_INNER);
            zvb[s] = __ldg(zp  + (size_t)lp * (2 * D_INNER));
            Bb[s]  = *(const float4*)(blp + (size_t)lp * 64);
            Cb[s]  = *(const float4*)(blp + (size_t)lp * 64 + D_STATE);
        }

        float dx = dtv * xv;
        float dA0 = __expf(dtv * A0);
        float dA1 = __expf(dtv * A1);
        float dA2 = __expf(dtv * A2);
        float dA3 = __expf(dtv * A3);
        h0 = fmaf(dA0, h0, dx * Bv.x);
        h1 = fmaf(dA1, h1, dx * Bv.y);
        h2 = fmaf(dA2, h2, dx * Bv.z);
        h3 = fmaf(dA3, h3, dx * Bv.w);
        float yv = h0 * Cv.x;
        yv = fmaf(h1, Cv.y, yv);
        yv = fmaf(h2, Cv.z, yv);
        yv = fmaf(h3, Cv.w, yv);
        yv += __shfl_xor_sync(0xffffffffu, yv, 1);
        yv += __shfl_xor_sync(0xffffffffu, yv, 2);
        if (sub == 0) {
            float yt = fmaf(Dv, xv, yv);
            float sg = 1.f / (1.f + __expf(-zv));
            yp[(size_t)l * D_INNER] = yt * (zv * sg);
        }
    }
}

// ---------------- host launcher ----------------
extern "C" void kernel_launch(void* const* d_in, const int* in_sizes, int n_in,
                              void* d_out, int out_size)
{
    const float* x      = (const float*)d_in[0];
    const float* ln_g   = (const float*)d_in[1];
    const float* ln_b   = (const float*)d_in[2];
    const float* in_w   = (const float*)d_in[3];
    const float* conv_w = (const float*)d_in[4];
    const float* conv_b = (const float*)d_in[5];
    const float* xp_w   = (const float*)d_in[6];
    const float* dt_w   = (const float*)d_in[7];
    const float* dt_b   = (const float*)d_in[8];
    const float* A_log  = (const float*)d_in[9];
    const float* Dp     = (const float*)d_in[10];
    const float* out_w  = (const float*)d_in[11];
    float* out = (float*)d_out;

    float *xn, *xz, *xc, *dbl, *dtb, *yb;
    cudaGetSymbolAddress((void**)&xn,  g_xn);
    cudaGetSymbolAddress((void**)&xz,  g_xz);
    cudaGetSymbolAddress((void**)&xc,  g_xc);
    cudaGetSymbolAddress((void**)&dbl, g_dbl);
    cudaGetSymbolAddress((void**)&dtb, g_dt);
    cudaGetSymbolAddress((void**)&yb,  g_y);

    // residual stream lives in d_out
    cudaMemcpyAsync(out, x, (size_t)M_TOK * D_MODEL * sizeof(float),
                    cudaMemcpyDeviceToDevice);

    for (int i = 0; i < N_LAYERS; ++i) {
        // 1) layernorm: 4096 rows, warp per row
        ln_kernel<<<M_TOK / 8, 256>>>(out, ln_g + (size_t)i * D_MODEL,
                                      ln_b + (size_t)i * D_MODEL, xn);

        // 2) in_proj: xz[4096,2048] = xn[4096,512] @ in_w^T
        gemm_kernel<128, 64, 16, 8, 4, 0><<<dim3(2 * D_INNER / 64, M_TOK / 128), 256>>>(
            xn, D_MODEL, in_w + (size_t)i * 2 * D_INNER * D_MODEL, D_MODEL,
            xz, 2 * D_INNER, M_TOK, 2 * D_INNER, D_MODEL, nullptr);

        // 3) conv(k=4, causal) + bias + silu -> xc
        conv_silu_kernel<<<(M_TOK * D_INNER) / 256, 256>>>(
            xz, conv_w + (size_t)i * D_INNER * D_CONV,
            conv_b + (size_t)i * D_INNER, xc);

        // 4) x_proj: dbl[4096,64] = xc[4096,1024] @ xp_w^T  (thin N -> small tiles)
        gemm_kernel<32, 64, 16, 2, 4, 0><<<dim3(1, M_TOK / 32), 256>>>(
            xc, D_INNER, xp_w + (size_t)i * 64 * D_INNER, D_INNER,
            dbl, 64, M_TOK, 64, D_INNER, nullptr);

        // 5) dt: softplus(dtr[4096,32] @ dt_w^T + dt_b) -> dt[4096,1024]
        gemm_kernel<128, 64, 16, 8, 4, 1><<<dim3(D_INNER / 64, M_TOK / 128), 256>>>(
            dbl, 64, dt_w + (size_t)i * D_INNER * DT_RANK, DT_RANK,
            dtb, D_INNER, M_TOK, D_INNER, DT_RANK, dt_b + (size_t)i * D_INNER);

        // 6) selective scan (fused D-skip + silu(z) gate) -> y
        scan_kernel<<<(M_TOK * 4) / 256, 256>>>(
            dtb, dbl, xc, xz, A_log + (size_t)i * D_INNER * D_STATE,
            Dp + (size_t)i * D_INNER, yb);

        // 7) out_proj with residual accumulate: out += y @ out_w^T
        gemm_kernel<128, 64, 16, 8, 4, 2><<<dim3(D_MODEL / 64, M_TOK / 128), 256>>>(
            yb, D_INNER, out_w + (size_t)i * D_MODEL * D_INNER, D_INNER,
            out, D_MODEL, M_TOK, D_MODEL, D_INNER, nullptr);
    }
    (void)in_sizes; (void)n_in; (void)out_size;
}

// round 9
// speedup vs baseline: 1.3009x; 1.3009x over previous
#include <cuda_runtime.h>
#include <cuda_bf16.h>
#include <cstdint>

// ---------------- problem constants ----------------
#define D_MODEL   512
#define N_LAYERS  4
#define D_STATE   16
#define D_CONV    4
#define D_INNER   1024
#define DT_RANK   32
#define BATCH     4
#define SEQ       1024
#define M_TOK     (BATCH * SEQ)          // 4096 tokens

// ---------------- scratch (device globals; no cudaMalloc allowed) ----------------
__device__ float g_xz [M_TOK * 2 * D_INNER];  // in_proj output (xc_pre | z)
__device__ float g_xc [M_TOK * D_INNER];      // conv+silu output (fp32, for scan)
__device__ float g_dbl[M_TOK * 64];           // x_proj output (dtr|B|C)
__device__ float g_dt [M_TOK * D_INNER];      // softplus dt

// bf16 split operands: activation = [hi | hi | lo], weight = [hi | lo | hi] over 3K
__device__ __nv_bfloat16 g_a2xn[M_TOK * 3 * D_MODEL];
__device__ __nv_bfloat16 g_a2xc[M_TOK * 3 * D_INNER];
__device__ __nv_bfloat16 g_a2y [M_TOK * 3 * D_INNER];
__device__ __nv_bfloat16 g_w2in [N_LAYERS * 2 * D_INNER * 3 * D_MODEL];
__device__ __nv_bfloat16 g_w2xp [N_LAYERS * 64 * 3 * D_INNER];
__device__ __nv_bfloat16 g_w2out[N_LAYERS * D_MODEL * 3 * D_INNER];

// ---------------- helpers ----------------
__device__ __forceinline__ void split2(float v, unsigned short& h, unsigned short& l) {
    __nv_bfloat16 hb = __float2bfloat16(v);
    float r = v - __bfloat162float(hb);
    __nv_bfloat16 lb = __float2bfloat16(r);
    h = __bfloat16_as_ushort(hb);
    l = __bfloat16_as_ushort(lb);
}

__device__ __forceinline__ void mma16816(float* c, const uint32_t* a, const uint32_t* b) {
    asm volatile(
        "mma.sync.aligned.m16n8k16.row.col.f32.bf16.bf16.f32 "
        "{%0,%1,%2,%3}, {%4,%5,%6,%7}, {%8,%9}, {%0,%1,%2,%3};"
        : "+f"(c[0]), "+f"(c[1]), "+f"(c[2]), "+f"(c[3])
        : "r"(a[0]), "r"(a[1]), "r"(a[2]), "r"(a[3]), "r"(b[0]), "r"(b[1]));
}

__device__ __forceinline__ void cp16(uint32_t smem_dst, const void* gsrc) {
    asm volatile("cp.async.cg.shared.global [%0], [%1], 16;" :: "r"(smem_dst), "l"(gsrc));
}

// ---------------- weight split: fp32 [R,K] -> bf16 [R, 3K] as (hi | lo | hi) --------------
__global__ __launch_bounds__(256) void wsplit_kernel(
    const float* __restrict__ in, __nv_bfloat16* __restrict__ out, int K, int total8)
{
    int t = blockIdx.x * 256 + threadIdx.x;
    if (t >= total8) return;
    int k0 = (t * 8) % K;
    int r  = (t * 8) / K;
    const float4* p = (const float4*)(in + (size_t)r * K + k0);
    float4 a = __ldg(p), b = __ldg(p + 1);
    float v[8] = {a.x, a.y, a.z, a.w, b.x, b.y, b.z, b.w};
    unsigned short h[8], l[8];
    #pragma unroll
    for (int i = 0; i < 8; i++) split2(v[i], h[i], l[i]);
    uint4 hv, lv;
    hv.x = h[0] | (h[1] << 16); hv.y = h[2] | (h[3] << 16);
    hv.z = h[4] | (h[5] << 16); hv.w = h[6] | (h[7] << 16);
    lv.x = l[0] | (l[1] << 16); lv.y = l[2] | (l[3] << 16);
    lv.z = l[4] | (l[5] << 16); lv.w = l[6] | (l[7] << 16);
    size_t base = (size_t)r * 3 * K + k0;
    *(uint4*)(out + base)         = hv;
    *(uint4*)(out + base + K)     = lv;
    *(uint4*)(out + base + 2 * K) = hv;
}

// ---------------- layernorm: one warp per row; writes bf16 split (hi|hi|lo) ----------------
__global__ __launch_bounds__(256) void ln_kernel(
    const float* __restrict__ x, const float* __restrict__ g,
    const float* __restrict__ b, __nv_bfloat16* __restrict__ a2)
{
    int warp = (blockIdx.x * blockDim.x + threadIdx.x) >> 5;
    int lane = threadIdx.x & 31;
    const float4* xr = (const float4*)(x + (size_t)warp * D_MODEL);
    float4 v[4];
    float s = 0.f;
    #pragma unroll
    for (int i = 0; i < 4; i++) {
        v[i] = __ldg(xr + lane + 32 * i);
        s += v[i].x + v[i].y + v[i].z + v[i].w;
    }
    #pragma unroll
    for (int o = 16; o; o >>= 1) s += __shfl_xor_sync(0xffffffffu, s, o);
    float mean = s * (1.0f / D_MODEL);
    float vs = 0.f;
    #pragma unroll
    for (int i = 0; i < 4; i++) {
        float dx;
        dx = v[i].x - mean; vs += dx * dx;
        dx = v[i].y - mean; vs += dx * dx;
        dx = v[i].z - mean; vs += dx * dx;
        dx = v[i].w - mean; vs += dx * dx;
    }
    #pragma unroll
    for (int o = 16; o; o >>= 1) vs += __shfl_xor_sync(0xffffffffu, vs, o);
    float inv = rsqrtf(vs * (1.0f / D_MODEL) + 1e-5f);

    const float4* g4 = (const float4*)g;
    const float4* b4 = (const float4*)b;
    __nv_bfloat16* row = a2 + (size_t)warp * (3 * D_MODEL);
    #pragma unroll
    for (int i = 0; i < 4; i++) {
        int idx = lane + 32 * i;
        float4 gv = __ldg(g4 + idx), bv = __ldg(b4 + idx), r;
        r.x = (v[i].x - mean) * inv * gv.x + bv.x;
        r.y = (v[i].y - mean) * inv * gv.y + bv.y;
        r.z = (v[i].z - mean) * inv * gv.z + bv.z;
        r.w = (v[i].w - mean) * inv * gv.w + bv.w;
        unsigned short h[4], l[4];
        split2(r.x, h[0], l[0]); split2(r.y, h[1], l[1]);
        split2(r.z, h[2], l[2]); split2(r.w, h[3], l[3]);
        uint32_t h01 = h[0] | (h[1] << 16), h23 = h[2] | (h[3] << 16);
        uint32_t l01 = l[0] | (l[1] << 16), l23 = l[2] | (l[3] << 16);
        int colb = idx * 4;
        uint32_t* p0 = (uint32_t*)(row + colb);
        uint32_t* p1 = (uint32_t*)(row + D_MODEL + colb);
        uint32_t* p2 = (uint32_t*)(row + 2 * D_MODEL + colb);
        p0[0] = h01; p0[1] = h23;
        p1[0] = h01; p1[1] = h23;
        p2[0] = l01; p2[1] = l23;
    }
}

// ---------------- HMMA bf16 GEMM: C[M,N] (+)= A2[M,K3] * W2[N,K3]^T --------------------
// mma.sync m16n8k16 bf16, fp32 accum. EPI: 0 = store, 2 = accumulate into C.
template<int BM, int BN, int WM, int WN, int EPI, int NT>
__global__ __launch_bounds__(NT) void hmma_gemm(
    const __nv_bfloat16* __restrict__ A, const __nv_bfloat16* __restrict__ W,
    float* __restrict__ C, int K3, int ldc)
{
    constexpr int BK    = 32;          // bf16 per k chunk
    constexpr int LDS   = BK + 8;      // padded row: 40 bf16 = 80B (16B aligned)
    __shared__ __nv_bfloat16 As[2][BM][LDS];
    __shared__ __nv_bfloat16 Ws[2][BN][LDS];

    const int tid  = threadIdx.x;
    const int wid  = tid >> 5, lane = tid & 31;
    constexpr int WARPS_N = BN / WN;
    const int wm0 = (wid / WARPS_N) * WM;
    const int wn0 = (wid % WARPS_N) * WN;
    const int m0 = blockIdx.y * BM, n0 = blockIdx.x * BN;
    const int gr = lane >> 2;               // 0..7
    const int ac = (lane & 3) * 2;          // 0,2,4,6

    constexpr int MT = WM / 16, NTL = WN / 8;
    float acc[MT][NTL][4];
    #pragma unroll
    for (int i = 0; i < MT; i++)
        #pragma unroll
        for (int j = 0; j < NTL; j++)
            acc[i][j][0] = acc[i][j][1] = acc[i][j][2] = acc[i][j][3] = 0.f;

    constexpr int TOT = (BM + BN) * 4;      // 16B chunks per stage

    auto load_stage = [&](int it, int s) {
        const int k0 = it * BK;
        #pragma unroll
        for (int i = 0; i < TOT / NT; ++i) {
            int ch = tid + i * NT;
            int row = ch >> 2, q = ch & 3;
            const __nv_bfloat16* g;
            uint32_t d;
            if (row < BM) {
                g = A + (size_t)(m0 + row) * K3 + k0 + q * 8;
                d = (uint32_t)__cvta_generic_to_shared(&As[s][row][q * 8]);
            } else {
                g = W + (size_t)(n0 + row - BM) * K3 + k0 + q * 8;
                d = (uint32_t)__cvta_generic_to_shared(&Ws[s][row - BM][q * 8]);
            }
            cp16(d, g);
        }
    };

    auto compute = [&](int s) {
        #pragma unroll
        for (int kk = 0; kk < 2; ++kk) {
            uint32_t af[MT][4], bf[NTL][2];
            #pragma unroll
            for (int mt = 0; mt < MT; ++mt) {
                const __nv_bfloat16* bm = &As[s][wm0 + mt * 16][kk * 16];
                af[mt][0] = *(const uint32_t*)&bm[(size_t)gr * LDS + ac];
                af[mt][1] = *(const uint32_t*)&bm[(size_t)(gr + 8) * LDS + ac];
                af[mt][2] = *(const uint32_t*)&bm[(size_t)gr * LDS + ac + 8];
                af[mt][3] = *(const uint32_t*)&bm[(size_t)(gr + 8) * LDS + ac + 8];
            }
            #pragma unroll
            for (int nt = 0; nt < NTL; ++nt) {
                const __nv_bfloat16* bn = &Ws[s][wn0 + nt * 8 + gr][kk * 16];
                bf[nt][0] = *(const uint32_t*)&bn[ac];
                bf[nt][1] = *(const uint32_t*)&bn[ac + 8];
            }
            #pragma unroll
            for (int mt = 0; mt < MT; ++mt)
                #pragma unroll
                for (int nt = 0; nt < NTL; ++nt)
                    mma16816(acc[mt][nt], af[mt], bf[nt]);
        }
    };

    const int NIT = K3 / BK;
    load_stage(0, 0);
    asm volatile("cp.async.commit_group;" ::: "memory");

    for (int it = 0; it < NIT; ++it) {
        int s = it & 1;
        if (it + 1 < NIT) {
            load_stage(it + 1, s ^ 1);
            asm volatile("cp.async.commit_group;" ::: "memory");
            asm volatile("cp.async.wait_group 1;" ::: "memory");
        } else {
            asm volatile("cp.async.wait_group 0;" ::: "memory");
        }
        __syncthreads();
        compute(s);
        __syncthreads();
    }

    // epilogue
    #pragma unroll
    for (int mt = 0; mt < MT; ++mt) {
        int r = m0 + wm0 + mt * 16 + gr;
        #pragma unroll
        for (int nt = 0; nt < NTL; ++nt) {
            int c = n0 + wn0 + nt * 8 + (lane & 3) * 2;
            float2* p0 = (float2*)&C[(size_t)r * ldc + c];
            float2* p1 = (float2*)&C[(size_t)(r + 8) * ldc + c];
            float2 v0 = make_float2(acc[mt][nt][0], acc[mt][nt][1]);
            float2 v1 = make_float2(acc[mt][nt][2], acc[mt][nt][3]);
            if (EPI == 2) {
                float2 o0 = *p0, o1 = *p1;
                v0.x += o0.x; v0.y += o0.y;
                v1.x += o1.x; v1.y += o1.y;
            }
            *p0 = v0;
            *p1 = v1;
        }
    }
}

// ---------------- SIMT GEMM (kept for dt: K=32, memory bound) ----------------
template<int BM, int BN, int BK, int TM, int TN, int EPI>
__global__ __launch_bounds__(256) void gemm_kernel(
    const float* __restrict__ A, int lda,
    const float* __restrict__ W, int ldb,
    float* __restrict__ C, int ldc,
    int M, int N, int K,
    const float* __restrict__ bias)
{
    __shared__ float As[BK][BM + 4];
    __shared__ float Wt[BK][BN + 4];

    const int tid = threadIdx.x;
    const int m0 = blockIdx.y * BM;
    const int n0 = blockIdx.x * BN;
    constexpr int NTX = BN / TN;
    const int tx = tid % NTX;
    const int ty = tid / NTX;

    float acc[TM][TN];
    #pragma unroll
    for (int i = 0; i < TM; i++)
        #pragma unroll
        for (int j = 0; j < TN; j++) acc[i][j] = 0.f;

    for (int k0 = 0; k0 < K; k0 += BK) {
        for (int i = tid; i < BM * BK; i += 256) {
            int m = i / BK, k = i % BK;
            As[k][m] = __ldg(A + (size_t)(m0 + m) * lda + k0 + k);
        }
        for (int i = tid; i < BN * BK; i += 256) {
            int n = i / BK, k = i % BK;
            Wt[k][n] = __ldg(W + (size_t)(n0 + n) * ldb + k0 + k);
        }
        __syncthreads();
        #pragma unroll
        for (int k = 0; k < BK; ++k) {
            float a[TM], bb[TN];
            #pragma unroll
            for (int i = 0; i < TM; i++) a[i] = As[k][ty * TM + i];
            #pragma unroll
            for (int j = 0; j < TN; j++) bb[j] = Wt[k][tx * TN + j];
            #pragma unroll
            for (int i = 0; i < TM; i++)
                #pragma unroll
                for (int j = 0; j < TN; j++)
                    acc[i][j] = fmaf(a[i], bb[j], acc[i][j]);
        }
        __syncthreads();
    }

    #pragma unroll
    for (int i = 0; i < TM; i++) {
        int m = m0 + ty * TM + i;
        #pragma unroll
        for (int j = 0; j < TN; j++) {
            int n = n0 + tx * TN + j;
            float v = acc[i][j];
            if (EPI == 1) {
                v += __ldg(bias + n);
                v = fmaxf(v, 0.f) + log1pf(expf(-fabsf(v)));
            } else if (EPI == 2) {
                v += C[(size_t)m * ldc + n];
            }
            C[(size_t)m * ldc + n] = v;
        }
    }
}

// ---------------- causal depthwise conv (k=4) + bias + silu; fp32 + bf16 split ----------
__global__ __launch_bounds__(256) void conv_silu_kernel(
    const float* __restrict__ xz, const float* __restrict__ cw,
    const float* __restrict__ cb, float* __restrict__ xc,
    __nv_bfloat16* __restrict__ a2)
{
    int idx = blockIdx.x * blockDim.x + threadIdx.x;
    int d  = idx & (D_INNER - 1);
    int tk = idx >> 10;
    int l  = tk & (SEQ - 1);
    int b  = tk >> 10;

    float4 w = __ldg((const float4*)cw + d);
    float acc = __ldg(cb + d);
    const float* base = xz + ((size_t)(b << 10)) * (2 * D_INNER) + d;
    #pragma unroll
    for (int k = 0; k < D_CONV; k++) {
        int lk = l - (D_CONV - 1) + k;
        if (lk >= 0) {
            float xv = __ldg(base + (size_t)lk * (2 * D_INNER));
            float wk = (k == 0) ? w.x : (k == 1) ? w.y : (k == 2) ? w.z : w.w;
            acc = fmaf(wk, xv, acc);
        }
    }
    float sg = 1.f / (1.f + __expf(-acc));
    float val = acc * sg;
    xc[idx] = val;
    unsigned short h, lo;
    split2(val, h, lo);
    __nv_bfloat16* rb = a2 + (size_t)tk * (3 * D_INNER);
    rb[d]               = __ushort_as_bfloat16(h);
    rb[D_INNER + d]     = __ushort_as_bfloat16(h);
    rb[2 * D_INNER + d] = __ushort_as_bfloat16(lo);
}

// ---------------- selective scan; epilogue writes bf16 split of gated y -----------------
__global__ __launch_bounds__(256) void scan_kernel(
    const float* __restrict__ dt, const float* __restrict__ dbl,
    const float* __restrict__ xc, const float* __restrict__ xz,
    const float* __restrict__ A_log, const float* __restrict__ Dp,
    __nv_bfloat16* __restrict__ a2y)
{
    int tid = blockIdx.x * blockDim.x + threadIdx.x;   // 16384 threads
    int sub = tid & 3;
    int ch  = tid >> 2;
    int d   = ch & (D_INNER - 1);
    int b   = ch >> 10;

    float A0 = -__expf(__ldg(A_log + d * D_STATE + sub * 4 + 0));
    float A1 = -__expf(__ldg(A_log + d * D_STATE + sub * 4 + 1));
    float A2 = -__expf(__ldg(A_log + d * D_STATE + sub * 4 + 2));
    float A3 = -__expf(__ldg(A_log + d * D_STATE + sub * 4 + 3));
    float Dv = __ldg(Dp + d);

    float h0 = 0.f, h1 = 0.f, h2 = 0.f, h3 = 0.f;

    const size_t tk0 = (size_t)(b << 10);
    const float* dtp = dt  + tk0 * D_INNER + d;
    const float* xcp = xc  + tk0 * D_INNER + d;
    const float* zp  = xz  + tk0 * (2 * D_INNER) + D_INNER + d;
    const float* blp = dbl + tk0 * 64 + DT_RANK + sub * 4;
    __nv_bfloat16* yp = a2y + tk0 * (3 * D_INNER) + d;

    const int PF = 4;
    float  dtb[PF], xvb[PF], zvb[PF];
    float4 Bb[PF], Cb[PF];
    #pragma unroll
    for (int i = 0; i < PF; i++) {
        dtb[i] = __ldg(dtp + (size_t)i * D_INNER);
        xvb[i] = __ldg(xcp + (size_t)i * D_INNER);
        zvb[i] = __ldg(zp  + (size_t)i * (2 * D_INNER));
        Bb[i]  = *(const float4*)(blp + (size_t)i * 64);
        Cb[i]  = *(const float4*)(blp + (size_t)i * 64 + D_STATE);
    }

    #pragma unroll 4
    for (int l = 0; l < SEQ; ++l) {
        int s = l & (PF - 1);
        float  dtv = dtb[s], xv = xvb[s], zv = zvb[s];
        float4 Bv = Bb[s], Cv = Cb[s];
        int lp = l + PF;
        if (lp < SEQ) {
            dtb[s] = __ldg(dtp + (size_t)lp * D_INNER);
            xvb[s] = __ldg(xcp + (size_t)lp * D_INNER);
            zvb[s] = __ldg(zp  + (size_t)lp * (2 * D_INNER));
            Bb[s]  = *(const float4*)(blp + (size_t)lp * 64);
            Cb[s]  = *(const float4*)(blp + (size_t)lp * 64 + D_STATE);
        }

        float dx = dtv * xv;
        float dA0 = __expf(dtv * A0);
        float dA1 = __expf(dtv * A1);
        float dA2 = __expf(dtv * A2);
        float dA3 = __expf(dtv * A3);
        h0 = fmaf(dA0, h0, dx * Bv.x);
        h1 = fmaf(dA1, h1, dx * Bv.y);
        h2 = fmaf(dA2, h2, dx * Bv.z);
        h3 = fmaf(dA3, h3, dx * Bv.w);
        float yv = h0 * Cv.x;
        yv = fmaf(h1, Cv.y, yv);
        yv = fmaf(h2, Cv.z, yv);
        yv = fmaf(h3, Cv.w, yv);
        yv += __shfl_xor_sync(0xffffffffu, yv, 1);
        yv += __shfl_xor_sync(0xffffffffu, yv, 2);
        if (sub == 0) {
            float yt = fmaf(Dv, xv, yv);
            float sg = 1.f / (1.f + __expf(-zv));
            float val = yt * (zv * sg);
            unsigned short hh, ll;
            split2(val, hh, ll);
            size_t rb = (size_t)l * (3 * D_INNER);
            yp[rb]               = __ushort_as_bfloat16(hh);
            yp[rb + D_INNER]     = __ushort_as_bfloat16(hh);
            yp[rb + 2 * D_INNER] = __ushort_as_bfloat16(ll);
        }
    }
}

// ---------------- host launcher ----------------
extern "C" void kernel_launch(void* const* d_in, const int* in_sizes, int n_in,
                              void* d_out, int out_size)
{
    const float* x      = (const float*)d_in[0];
    const float* ln_g   = (const float*)d_in[1];
    const float* ln_b   = (const float*)d_in[2];
    const float* in_w   = (const float*)d_in[3];
    const float* conv_w = (const float*)d_in[4];
    const float* conv_b = (const float*)d_in[5];
    const float* xp_w   = (const float*)d_in[6];
    const float* dt_w   = (const float*)d_in[7];
    const float* dt_b   = (const float*)d_in[8];
    const float* A_log  = (const float*)d_in[9];
    const float* Dp     = (const float*)d_in[10];
    const float* out_w  = (const float*)d_in[11];
    float* out = (float*)d_out;

    float *xz, *xc, *dbl, *dtb;
    __nv_bfloat16 *a2xn, *a2xc, *a2y, *w2in, *w2xp, *w2out;
    cudaGetSymbolAddress((void**)&xz,   g_xz);
    cudaGetSymbolAddress((void**)&xc,   g_xc);
    cudaGetSymbolAddress((void**)&dbl,  g_dbl);
    cudaGetSymbolAddress((void**)&dtb,  g_dt);
    cudaGetSymbolAddress((void**)&a2xn, g_a2xn);
    cudaGetSymbolAddress((void**)&a2xc, g_a2xc);
    cudaGetSymbolAddress((void**)&a2y,  g_a2y);
    cudaGetSymbolAddress((void**)&w2in, g_w2in);
    cudaGetSymbolAddress((void**)&w2xp, g_w2xp);
    cudaGetSymbolAddress((void**)&w2out,g_w2out);

    // weight splits (all layers)
    wsplit_kernel<<<2048, 256>>>(in_w,  w2in,  D_MODEL, (N_LAYERS * 2 * D_INNER * D_MODEL) / 8);
    wsplit_kernel<<<128,  256>>>(xp_w,  w2xp,  D_INNER, (N_LAYERS * 64 * D_INNER) / 8);
    wsplit_kernel<<<1024, 256>>>(out_w, w2out, D_INNER, (N_LAYERS * D_MODEL * D_INNER) / 8);

    // residual stream lives in d_out
    cudaMemcpyAsync(out, x, (size_t)M_TOK * D_MODEL * sizeof(float),
                    cudaMemcpyDeviceToDevice);

    for (int i = 0; i < N_LAYERS; ++i) {
        // 1) layernorm -> bf16 split a2xn
        ln_kernel<<<M_TOK / 8, 256>>>(out, ln_g + (size_t)i * D_MODEL,
                                      ln_b + (size_t)i * D_MODEL, a2xn);

        // 2) in_proj (HMMA): xz[4096,2048], K3 = 1536
        hmma_gemm<128, 128, 64, 32, 0, 256><<<dim3(2 * D_INNER / 128, M_TOK / 128), 256>>>(
            a2xn, w2in + (size_t)i * 2 * D_INNER * 3 * D_MODEL, xz, 3 * D_MODEL, 2 * D_INNER);

        // 3) conv + silu -> xc fp32 + bf16 split a2xc
        conv_silu_kernel<<<(M_TOK * D_INNER) / 256, 256>>>(
            xz, conv_w + (size_t)i * D_INNER * D_CONV,
            conv_b + (size_t)i * D_INNER, xc, a2xc);

        // 4) x_proj (HMMA): dbl[4096,64], K3 = 3072
        hmma_gemm<64, 64, 32, 32, 0, 128><<<dim3(1, M_TOK / 64), 128>>>(
            a2xc, w2xp + (size_t)i * 64 * 3 * D_INNER, dbl, 3 * D_INNER, 64);

        // 5) dt: softplus(dtr @ dt_w^T + dt_b)  (SIMT — K=32, memory bound)
        gemm_kernel<128, 64, 16, 8, 4, 1><<<dim3(D_INNER / 64, M_TOK / 128), 256>>>(
            dbl, 64, dt_w + (size_t)i * D_INNER * DT_RANK, DT_RANK,
            dtb, D_INNER, M_TOK, D_INNER, DT_RANK, dt_b + (size_t)i * D_INNER);

        // 6) selective scan -> bf16 split a2y (fused D-skip + silu(z) gate)
        scan_kernel<<<(M_TOK * 4) / 256, 256>>>(
            dtb, dbl, xc, xz, A_log + (size_t)i * D_INNER * D_STATE,
            Dp + (size_t)i * D_INNER, a2y);

        // 7) out_proj (HMMA) with residual accumulate, K3 = 3072
        hmma_gemm<128, 128, 64, 32, 2, 256><<<dim3(D_MODEL / 128, M_TOK / 128), 256>>>(
            a2y, w2out + (size_t)i * D_MODEL * 3 * D_INNER, out, 3 * D_INNER, D_MODEL);
    }
    (void)in_sizes; (void)n_in; (void)out_size;
}

// round 10
// speedup vs baseline: 1.4547x; 1.1182x over previous
#include <cuda_runtime.h>
#include <cuda_bf16.h>
#include <cstdint>

// ---------------- problem constants ----------------
#define D_MODEL   512
#define N_LAYERS  4
#define D_STATE   16
#define D_CONV    4
#define D_INNER   1024
#define DT_RANK   32
#define BATCH     4
#define SEQ       1024
#define M_TOK     (BATCH * SEQ)          // 4096 tokens

// ---------------- scratch (device globals; no cudaMalloc allowed) ----------------
__device__ float g_xz [M_TOK * 2 * D_INNER];  // in_proj output (xc_pre | z)
__device__ float g_xc [M_TOK * D_INNER];      // conv+silu output (fp32, for scan)
__device__ float g_dbl[M_TOK * 64];           // x_proj output (dtr|B|C)
__device__ float g_dt [M_TOK * D_INNER];      // softplus dt

// bf16 split operands: activation = [hi | hi | lo], weight = [hi | lo | hi] over 3K
__device__ __nv_bfloat16 g_a2xn[M_TOK * 3 * D_MODEL];
__device__ __nv_bfloat16 g_a2xc[M_TOK * 3 * D_INNER];
__device__ __nv_bfloat16 g_a2y [M_TOK * 3 * D_INNER];
__device__ __nv_bfloat16 g_w2in [N_LAYERS * 2 * D_INNER * 3 * D_MODEL];
__device__ __nv_bfloat16 g_w2xp [N_LAYERS * 64 * 3 * D_INNER];
__device__ __nv_bfloat16 g_w2out[N_LAYERS * D_MODEL * 3 * D_INNER];

// ---------------- helpers ----------------
__device__ __forceinline__ void split2(float v, unsigned short& h, unsigned short& l) {
    __nv_bfloat16 hb = __float2bfloat16(v);
    float r = v - __bfloat162float(hb);
    __nv_bfloat16 lb = __float2bfloat16(r);
    h = __bfloat16_as_ushort(hb);
    l = __bfloat16_as_ushort(lb);
}

__device__ __forceinline__ void mma16816(float* c, const uint32_t* a, const uint32_t* b) {
    asm volatile(
        "mma.sync.aligned.m16n8k16.row.col.f32.bf16.bf16.f32 "
        "{%0,%1,%2,%3}, {%4,%5,%6,%7}, {%8,%9}, {%0,%1,%2,%3};"
        : "+f"(c[0]), "+f"(c[1]), "+f"(c[2]), "+f"(c[3])
        : "r"(a[0]), "r"(a[1]), "r"(a[2]), "r"(a[3]), "r"(b[0]), "r"(b[1]));
}

__device__ __forceinline__ void cp16(uint32_t smem_dst, const void* gsrc) {
    asm volatile("cp.async.cg.shared.global [%0], [%1], 16;" :: "r"(smem_dst), "l"(gsrc));
}

__device__ __forceinline__ void ldsm4(uint32_t* r, uint32_t a) {
    asm volatile("ldmatrix.sync.aligned.m8n8.x4.shared.b16 {%0,%1,%2,%3}, [%4];"
                 : "=r"(r[0]), "=r"(r[1]), "=r"(r[2]), "=r"(r[3]) : "r"(a));
}

// ---------------- weight split: fp32 [R,K] -> bf16 [R, 3K] as (hi | lo | hi) --------------
__global__ __launch_bounds__(256) void wsplit_kernel(
    const float* __restrict__ in, __nv_bfloat16* __restrict__ out, int K, int total8)
{
    int t = blockIdx.x * 256 + threadIdx.x;
    if (t >= total8) return;
    int k0 = (t * 8) % K;
    int r  = (t * 8) / K;
    const float4* p = (const float4*)(in + (size_t)r * K + k0);
    float4 a = __ldg(p), b = __ldg(p + 1);
    float v[8] = {a.x, a.y, a.z, a.w, b.x, b.y, b.z, b.w};
    unsigned short h[8], l[8];
    #pragma unroll
    for (int i = 0; i < 8; i++) split2(v[i], h[i], l[i]);
    uint4 hv, lv;
    hv.x = h[0] | (h[1] << 16); hv.y = h[2] | (h[3] << 16);
    hv.z = h[4] | (h[5] << 16); hv.w = h[6] | (h[7] << 16);
    lv.x = l[0] | (l[1] << 16); lv.y = l[2] | (l[3] << 16);
    lv.z = l[4] | (l[5] << 16); lv.w = l[6] | (l[7] << 16);
    size_t base = (size_t)r * 3 * K + k0;
    *(uint4*)(out + base)         = hv;
    *(uint4*)(out + base + K)     = lv;
    *(uint4*)(out + base + 2 * K) = hv;
}

// ---------------- layernorm: one warp per row; writes bf16 split (hi|hi|lo) ----------------
__global__ __launch_bounds__(256) void ln_kernel(
    const float* __restrict__ x, const float* __restrict__ g,
    const float* __restrict__ b, __nv_bfloat16* __restrict__ a2)
{
    int warp = (blockIdx.x * blockDim.x + threadIdx.x) >> 5;
    int lane = threadIdx.x & 31;
    const float4* xr = (const float4*)(x + (size_t)warp * D_MODEL);
    float4 v[4];
    float s = 0.f;
    #pragma unroll
    for (int i = 0; i < 4; i++) {
        v[i] = __ldg(xr + lane + 32 * i);
        s += v[i].x + v[i].y + v[i].z + v[i].w;
    }
    #pragma unroll
    for (int o = 16; o; o >>= 1) s += __shfl_xor_sync(0xffffffffu, s, o);
    float mean = s * (1.0f / D_MODEL);
    float vs = 0.f;
    #pragma unroll
    for (int i = 0; i < 4; i++) {
        float dx;
        dx = v[i].x - mean; vs += dx * dx;
        dx = v[i].y - mean; vs += dx * dx;
        dx = v[i].z - mean; vs += dx * dx;
        dx = v[i].w - mean; vs += dx * dx;
    }
    #pragma unroll
    for (int o = 16; o; o >>= 1) vs += __shfl_xor_sync(0xffffffffu, vs, o);
    float inv = rsqrtf(vs * (1.0f / D_MODEL) + 1e-5f);

    const float4* g4 = (const float4*)g;
    const float4* b4 = (const float4*)b;
    __nv_bfloat16* row = a2 + (size_t)warp * (3 * D_MODEL);
    #pragma unroll
    for (int i = 0; i < 4; i++) {
        int idx = lane + 32 * i;
        float4 gv = __ldg(g4 + idx), bv = __ldg(b4 + idx), r;
        r.x = (v[i].x - mean) * inv * gv.x + bv.x;
        r.y = (v[i].y - mean) * inv * gv.y + bv.y;
        r.z = (v[i].z - mean) * inv * gv.z + bv.z;
        r.w = (v[i].w - mean) * inv * gv.w + bv.w;
        unsigned short h[4], l[4];
        split2(r.x, h[0], l[0]); split2(r.y, h[1], l[1]);
        split2(r.z, h[2], l[2]); split2(r.w, h[3], l[3]);
        uint32_t h01 = h[0] | (h[1] << 16), h23 = h[2] | (h[3] << 16);
        uint32_t l01 = l[0] | (l[1] << 16), l23 = l[2] | (l[3] << 16);
        int colb = idx * 4;
        uint32_t* p0 = (uint32_t*)(row + colb);
        uint32_t* p1 = (uint32_t*)(row + D_MODEL + colb);
        uint32_t* p2 = (uint32_t*)(row + 2 * D_MODEL + colb);
        p0[0] = h01; p0[1] = h23;
        p1[0] = h01; p1[1] = h23;
        p2[0] = l01; p2[1] = l23;
    }
}

// ---------------- HMMA bf16 GEMM: C[M,N] (+)= A2[M,K3] * W2[N,K3]^T --------------------
// BK=64, ldmatrix fragment loads, double-buffered cp.async.
// SMEM row = 64 bf16 + 8 pad = 144B (conflict-free for LDSM: 36r mod 32 covers all banks).
// EPI: 0 = store, 2 = accumulate into C.
template<int BM, int BN, int WM, int WN, int EPI, int NT>
__global__ __launch_bounds__(NT) void hmma_gemm(
    const __nv_bfloat16* __restrict__ A, const __nv_bfloat16* __restrict__ W,
    float* __restrict__ C, int K3, int ldc)
{
    constexpr int BK   = 64;
    constexpr int LDSB = 144;                 // bytes per smem row (64 bf16 + 8 pad)
    constexpr int STAGE = (BM + BN) * LDSB;
    extern __shared__ __align__(16) char sm[];

    const int tid  = threadIdx.x;
    const int wid  = tid >> 5, lane = tid & 31;
    constexpr int WARPS_N = BN / WN;
    const int wm0 = (wid / WARPS_N) * WM;
    const int wn0 = (wid % WARPS_N) * WN;
    const int m0 = blockIdx.y * BM, n0 = blockIdx.x * BN;

    constexpr int MT = WM / 16, NTL = WN / 8;
    float acc[MT][NTL][4];
    #pragma unroll
    for (int i = 0; i < MT; i++)
        #pragma unroll
        for (int j = 0; j < NTL; j++)
            acc[i][j][0] = acc[i][j][1] = acc[i][j][2] = acc[i][j][3] = 0.f;

    constexpr int TOT = (BM + BN) * 8;        // 16B chunks per stage (8 per row)

    auto load_stage = [&](int it, int s) {
        const int k0 = it * BK;
        #pragma unroll
        for (int i = 0; i < TOT / NT; ++i) {
            int ch = tid + i * NT;
            int row = ch >> 3, q = ch & 7;
            const __nv_bfloat16* g =
                (row < BM) ? A + (size_t)(m0 + row) * K3 + k0 + q * 8
                           : W + (size_t)(n0 + row - BM) * K3 + k0 + q * 8;
            uint32_t d = (uint32_t)__cvta_generic_to_shared(
                sm + s * STAGE + row * LDSB + q * 16);
            cp16(d, g);
        }
    };

    // ldmatrix address lanes
    const int ar = lane & 15, ak = (lane >> 4) * 8;          // A: x4 covers 16x16
    const int br = lane & 7,  bg = lane >> 3;                // B: x4 covers two n8xk16

    auto compute = [&](int s) {
        char* abase = sm + s * STAGE;
        char* wbase = abase + BM * LDSB;
        #pragma unroll
        for (int kk = 0; kk < 4; ++kk) {
            uint32_t af[MT][4], bf[NTL][2];
            #pragma unroll
            for (int mt = 0; mt < MT; ++mt) {
                uint32_t a = (uint32_t)__cvta_generic_to_shared(
                    abase + (size_t)(wm0 + mt * 16 + ar) * LDSB + (kk * 16 + ak) * 2);
                ldsm4(af[mt], a);
            }
            #pragma unroll
            for (int np = 0; np < NTL / 2; ++np) {
                int ntsel = np * 2 + (bg >> 1);
                int koff  = (bg & 1) * 8;
                uint32_t a = (uint32_t)__cvta_generic_to_shared(
                    wbase + (size_t)(wn0 + ntsel * 8 + br) * LDSB + (kk * 16 + koff) * 2);
                uint32_t r4[4];
                ldsm4(r4, a);
                bf[np * 2][0] = r4[0]; bf[np * 2][1] = r4[1];
                bf[np * 2 + 1][0] = r4[2]; bf[np * 2 + 1][1] = r4[3];
            }
            #pragma unroll
            for (int mt = 0; mt < MT; ++mt)
                #pragma unroll
                for (int nt = 0; nt < NTL; ++nt)
                    mma16816(acc[mt][nt], af[mt], bf[nt]);
        }
    };

    const int NIT = K3 / BK;
    load_stage(0, 0);
    asm volatile("cp.async.commit_group;" ::: "memory");

    for (int it = 0; it < NIT; ++it) {
        int s = it & 1;
        if (it + 1 < NIT) {
            load_stage(it + 1, s ^ 1);
            asm volatile("cp.async.commit_group;" ::: "memory");
            asm volatile("cp.async.wait_group 1;" ::: "memory");
        } else {
            asm volatile("cp.async.wait_group 0;" ::: "memory");
        }
        __syncthreads();
        compute(s);
        __syncthreads();
    }

    // epilogue
    const int gr = lane >> 2;
    #pragma unroll
    for (int mt = 0; mt < MT; ++mt) {
        int r = m0 + wm0 + mt * 16 + gr;
        #pragma unroll
        for (int nt = 0; nt < NTL; ++nt) {
            int c = n0 + wn0 + nt * 8 + (lane & 3) * 2;
            float2* p0 = (float2*)&C[(size_t)r * ldc + c];
            float2* p1 = (float2*)&C[(size_t)(r + 8) * ldc + c];
            float2 v0 = make_float2(acc[mt][nt][0], acc[mt][nt][1]);
            float2 v1 = make_float2(acc[mt][nt][2], acc[mt][nt][3]);
            if (EPI == 2) {
                float2 o0 = *p0, o1 = *p1;
                v0.x += o0.x; v0.y += o0.y;
                v1.x += o1.x; v1.y += o1.y;
            }
            *p0 = v0;
            *p1 = v1;
        }
    }
}

// ---------------- SIMT GEMM (kept for dt: K=32, memory bound) ----------------
template<int BM, int BN, int BK, int TM, int TN, int EPI>
__global__ __launch_bounds__(256) void gemm_kernel(
    const float* __restrict__ A, int lda,
    const float* __restrict__ W, int ldb,
    float* __restrict__ C, int ldc,
    int M, int N, int K,
    const float* __restrict__ bias)
{
    __shared__ float As[BK][BM + 4];
    __shared__ float Wt[BK][BN + 4];

    const int tid = threadIdx.x;
    const int m0 = blockIdx.y * BM;
    const int n0 = blockIdx.x * BN;
    constexpr int NTX = BN / TN;
    const int tx = tid % NTX;
    const int ty = tid / NTX;

    float acc[TM][TN];
    #pragma unroll
    for (int i = 0; i < TM; i++)
        #pragma unroll
        for (int j = 0; j < TN; j++) acc[i][j] = 0.f;

    for (int k0 = 0; k0 < K; k0 += BK) {
        for (int i = tid; i < BM * BK; i += 256) {
            int m = i / BK, k = i % BK;
            As[k][m] = __ldg(A + (size_t)(m0 + m) * lda + k0 + k);
        }
        for (int i = tid; i < BN * BK; i += 256) {
            int n = i / BK, k = i % BK;
            Wt[k][n] = __ldg(W + (size_t)(n0 + n) * ldb + k0 + k);
        }
        __syncthreads();
        #pragma unroll
        for (int k = 0; k < BK; ++k) {
            float a[TM], bb[TN];
            #pragma unroll
            for (int i = 0; i < TM; i++) a[i] = As[k][ty * TM + i];
            #pragma unroll
            for (int j = 0; j < TN; j++) bb[j] = Wt[k][tx * TN + j];
            #pragma unroll
            for (int i = 0; i < TM; i++)
                #pragma unroll
                for (int j = 0; j < TN; j++)
                    acc[i][j] = fmaf(a[i], bb[j], acc[i][j]);
        }
        __syncthreads();
    }

    #pragma unroll
    for (int i = 0; i < TM; i++) {
        int m = m0 + ty * TM + i;
        #pragma unroll
        for (int j = 0; j < TN; j++) {
            int n = n0 + tx * TN + j;
            float v = acc[i][j];
            if (EPI == 1) {
                v += __ldg(bias + n);
                v = fmaxf(v, 0.f) + log1pf(expf(-fabsf(v)));
            } else if (EPI == 2) {
                v += C[(size_t)m * ldc + n];
            }
            C[(size_t)m * ldc + n] = v;
        }
    }
}

// ---------------- causal depthwise conv (k=4) + bias + silu; fp32 + bf16 split ----------
__global__ __launch_bounds__(256) void conv_silu_kernel(
    const float* __restrict__ xz, const float* __restrict__ cw,
    const float* __restrict__ cb, float* __restrict__ xc,
    __nv_bfloat16* __restrict__ a2)
{
    int idx = blockIdx.x * blockDim.x + threadIdx.x;
    int d  = idx & (D_INNER - 1);
    int tk = idx >> 10;
    int l  = tk & (SEQ - 1);
    int b  = tk >> 10;

    float4 w = __ldg((const float4*)cw + d);
    float acc = __ldg(cb + d);
    const float* base = xz + ((size_t)(b << 10)) * (2 * D_INNER) + d;
    #pragma unroll
    for (int k = 0; k < D_CONV; k++) {
        int lk = l - (D_CONV - 1) + k;
        if (lk >= 0) {
            float xv = __ldg(base + (size_t)lk * (2 * D_INNER));
            float wk = (k == 0) ? w.x : (k == 1) ? w.y : (k == 2) ? w.z : w.w;
            acc = fmaf(wk, xv, acc);
        }
    }
    float sg = 1.f / (1.f + __expf(-acc));
    float val = acc * sg;
    xc[idx] = val;
    unsigned short h, lo;
    split2(val, h, lo);
    __nv_bfloat16* rb = a2 + (size_t)tk * (3 * D_INNER);
    rb[d]               = __ushort_as_bfloat16(h);
    rb[D_INNER + d]     = __ushort_as_bfloat16(h);
    rb[2 * D_INNER + d] = __ushort_as_bfloat16(lo);
}

// ---------------- selective scan; 64-thread blocks spread over all SMs -----------------
__global__ __launch_bounds__(64) void scan_kernel(
    const float* __restrict__ dt, const float* __restrict__ dbl,
    const float* __restrict__ xc, const float* __restrict__ xz,
    const float* __restrict__ A_log, const float* __restrict__ Dp,
    __nv_bfloat16* __restrict__ a2y)
{
    int tid = blockIdx.x * blockDim.x + threadIdx.x;   // 16384 threads
    int sub = tid & 3;
    int ch  = tid >> 2;
    int d   = ch & (D_INNER - 1);
    int b   = ch >> 10;

    float A0 = -__expf(__ldg(A_log + d * D_STATE + sub * 4 + 0));
    float A1 = -__expf(__ldg(A_log + d * D_STATE + sub * 4 + 1));
    float A2 = -__expf(__ldg(A_log + d * D_STATE + sub * 4 + 2));
    float A3 = -__expf(__ldg(A_log + d * D_STATE + sub * 4 + 3));
    float Dv = __ldg(Dp + d);

    float h0 = 0.f, h1 = 0.f, h2 = 0.f, h3 = 0.f;

    const size_t tk0 = (size_t)(b << 10);
    const float* dtp = dt  + tk0 * D_INNER + d;
    const float* xcp = xc  + tk0 * D_INNER + d;
    const float* zp  = xz  + tk0 * (2 * D_INNER) + D_INNER + d;
    const float* blp = dbl + tk0 * 64 + DT_RANK + sub * 4;
    __nv_bfloat16* yp = a2y + tk0 * (3 * D_INNER) + d;

    const int PF = 4;
    float  dtb[PF], xvb[PF], zvb[PF];
    float4 Bb[PF], Cb[PF];
    #pragma unroll
    for (int i = 0; i < PF; i++) {
        dtb[i] = __ldg(dtp + (size_t)i * D_INNER);
        xvb[i] = __ldg(xcp + (size_t)i * D_INNER);
        zvb[i] = __ldg(zp  + (size_t)i * (2 * D_INNER));
        Bb[i]  = *(const float4*)(blp + (size_t)i * 64);
        Cb[i]  = *(const float4*)(blp + (size_t)i * 64 + D_STATE);
    }

    #pragma unroll 4
    for (int l = 0; l < SEQ; ++l) {
        int s = l & (PF - 1);
        float  dtv = dtb[s], xv = xvb[s], zv = zvb[s];
        float4 Bv = Bb[s], Cv = Cb[s];
        int lp = l + PF;
        if (lp < SEQ) {
            dtb[s] = __ldg(dtp + (size_t)lp * D_INNER);
            xvb[s] = __ldg(xcp + (size_t)lp * D_INNER);
            zvb[s] = __ldg(zp  + (size_t)lp * (2 * D_INNER));
            Bb[s]  = *(const float4*)(blp + (size_t)lp * 64);
            Cb[s]  = *(const float4*)(blp + (size_t)lp * 64 + D_STATE);
        }

        float dx = dtv * xv;
        float dA0 = __expf(dtv * A0);
        float dA1 = __expf(dtv * A1);
        float dA2 = __expf(dtv * A2);
        float dA3 = __expf(dtv * A3);
        h0 = fmaf(dA0, h0, dx * Bv.x);
        h1 = fmaf(dA1, h1, dx * Bv.y);
        h2 = fmaf(dA2, h2, dx * Bv.z);
        h3 = fmaf(dA3, h3, dx * Bv.w);
        float yv = h0 * Cv.x;
        yv = fmaf(h1, Cv.y, yv);
        yv = fmaf(h2, Cv.z, yv);
        yv = fmaf(h3, Cv.w, yv);
        yv += __shfl_xor_sync(0xffffffffu, yv, 1);
        yv += __shfl_xor_sync(0xffffffffu, yv, 2);
        if (sub == 0) {
            float yt = fmaf(Dv, xv, yv);
            float sg = 1.f / (1.f + __expf(-zv));
            float val = yt * (zv * sg);
            unsigned short hh, ll;
            split2(val, hh, ll);
            size_t rb = (size_t)l * (3 * D_INNER);
            yp[rb]               = __ushort_as_bfloat16(hh);
            yp[rb + D_INNER]     = __ushort_as_bfloat16(hh);
            yp[rb + 2 * D_INNER] = __ushort_as_bfloat16(ll);
        }
    }
}

// ---------------- host launcher ----------------
extern "C" void kernel_launch(void* const* d_in, const int* in_sizes, int n_in,
                              void* d_out, int out_size)
{
    const float* x      = (const float*)d_in[0];
    const float* ln_g   = (const float*)d_in[1];
    const float* ln_b   = (const float*)d_in[2];
    const float* in_w   = (const float*)d_in[3];
    const float* conv_w = (const float*)d_in[4];
    const float* conv_b = (const float*)d_in[5];
    const float* xp_w   = (const float*)d_in[6];
    const float* dt_w   = (const float*)d_in[7];
    const float* dt_b   = (const float*)d_in[8];
    const float* A_log  = (const float*)d_in[9];
    const float* Dp     = (const float*)d_in[10];
    const float* out_w  = (const float*)d_in[11];
    float* out = (float*)d_out;

    float *xz, *xc, *dbl, *dtb;
    __nv_bfloat16 *a2xn, *a2xc, *a2y, *w2in, *w2xp, *w2out;
    cudaGetSymbolAddress((void**)&xz,   g_xz);
    cudaGetSymbolAddress((void**)&xc,   g_xc);
    cudaGetSymbolAddress((void**)&dbl,  g_dbl);
    cudaGetSymbolAddress((void**)&dtb,  g_dt);
    cudaGetSymbolAddress((void**)&a2xn, g_a2xn);
    cudaGetSymbolAddress((void**)&a2xc, g_a2xc);
    cudaGetSymbolAddress((void**)&a2y,  g_a2y);
    cudaGetSymbolAddress((void**)&w2in, g_w2in);
    cudaGetSymbolAddress((void**)&w2xp, g_w2xp);
    cudaGetSymbolAddress((void**)&w2out,g_w2out);

    // dynamic smem: 2 stages x (BM+BN) x 144B
    constexpr int SMEM_BIG = 2 * (128 + 128) * 144;   // 73728
    constexpr int SMEM_XP  = 2 * (32 + 64) * 144;     // 27648
    cudaFuncSetAttribute(hmma_gemm<128, 128, 64, 32, 0, 256>,
                         cudaFuncAttributeMaxDynamicSharedMemorySize, SMEM_BIG);
    cudaFuncSetAttribute(hmma_gemm<128, 128, 64, 32, 2, 256>,
                         cudaFuncAttributeMaxDynamicSharedMemorySize, SMEM_BIG);

    // weight splits (all layers)
    wsplit_kernel<<<2048, 256>>>(in_w,  w2in,  D_MODEL, (N_LAYERS * 2 * D_INNER * D_MODEL) / 8);
    wsplit_kernel<<<128,  256>>>(xp_w,  w2xp,  D_INNER, (N_LAYERS * 64 * D_INNER) / 8);
    wsplit_kernel<<<1024, 256>>>(out_w, w2out, D_INNER, (N_LAYERS * D_MODEL * D_INNER) / 8);

    // residual stream lives in d_out
    cudaMemcpyAsync(out, x, (size_t)M_TOK * D_MODEL * sizeof(float),
                    cudaMemcpyDeviceToDevice);

    for (int i = 0; i < N_LAYERS; ++i) {
        // 1) layernorm -> bf16 split a2xn
        ln_kernel<<<M_TOK / 8, 256>>>(out, ln_g + (size_t)i * D_MODEL,
                                      ln_b + (size_t)i * D_MODEL, a2xn);

        // 2) in_proj (HMMA): xz[4096,2048], K3 = 1536
        hmma_gemm<128, 128, 64, 32, 0, 256>
            <<<dim3(2 * D_INNER / 128, M_TOK / 128), 256, SMEM_BIG>>>(
            a2xn, w2in + (size_t)i * 2 * D_INNER * 3 * D_MODEL, xz, 3 * D_MODEL, 2 * D_INNER);

        // 3) conv + silu -> xc fp32 + bf16 split a2xc
        conv_silu_kernel<<<(M_TOK * D_INNER) / 256, 256>>>(
            xz, conv_w + (size_t)i * D_INNER * D_CONV,
            conv_b + (size_t)i * D_INNER, xc, a2xc);

        // 4) x_proj (HMMA): dbl[4096,64], K3 = 3072, 128 CTAs
        hmma_gemm<32, 64, 16, 32, 0, 128>
            <<<dim3(1, M_TOK / 32), 128, SMEM_XP>>>(
            a2xc, w2xp + (size_t)i * 64 * 3 * D_INNER, dbl, 3 * D_INNER, 64);

        // 5) dt: softplus(dtr @ dt_w^T + dt_b)  (SIMT — K=32, memory bound)
        gemm_kernel<128, 64, 16, 8, 4, 1><<<dim3(D_INNER / 64, M_TOK / 128), 256>>>(
            dbl, 64, dt_w + (size_t)i * D_INNER * DT_RANK, DT_RANK,
            dtb, D_INNER, M_TOK, D_INNER, DT_RANK, dt_b + (size_t)i * D_INNER);

        // 6) selective scan -> bf16 split a2y (fused D-skip + silu(z) gate)
        scan_kernel<<<(M_TOK * 4) / 64, 64>>>(
            dtb, dbl, xc, xz, A_log + (size_t)i * D_INNER * D_STATE,
            Dp + (size_t)i * D_INNER, a2y);

        // 7) out_proj (HMMA) with residual accumulate, K3 = 3072
        hmma_gemm<128, 128, 64, 32, 2, 256>
            <<<dim3(D_MODEL / 128, M_TOK / 128), 256, SMEM_BIG>>>(
            a2y, w2out + (size_t)i * D_MODEL * 3 * D_INNER, out, 3 * D_INNER, D_MODEL);
    }
    (void)in_sizes; (void)n_in; (void)out_size;
}

// round 11
// speedup vs baseline: 1.9829x; 1.3632x over previous
#include <cuda_runtime.h>
#include <cuda_fp16.h>
#include <cstdint>

// ---------------- problem constants ----------------
#define D_MODEL   512
#define N_LAYERS  4
#define D_STATE   16
#define D_CONV    4
#define D_INNER   1024
#define DT_RANK   32
#define BATCH     4
#define SEQ       1024
#define M_TOK     (BATCH * SEQ)          // 4096 tokens

// ---------------- scratch (device globals; no cudaMalloc allowed) ----------------
__device__ float g_xz [M_TOK * 2 * D_INNER];  // in_proj output (xc_pre | z)
__device__ float g_xc [M_TOK * D_INNER];      // conv+silu output (fp32, for scan)
__device__ float g_dbl[M_TOK * 64];           // x_proj output (dtr|B|C)
__device__ float g_dt [M_TOK * D_INNER];      // softplus dt

// fp16 GEMM operands (single precision pass — no split)
__device__ __half g_hxn[M_TOK * D_MODEL];
__device__ __half g_hxc[M_TOK * D_INNER];
__device__ __half g_hy [M_TOK * D_INNER];
__device__ __half g_hwin [N_LAYERS * 2 * D_INNER * D_MODEL];
__device__ __half g_hwxp [N_LAYERS * 64 * D_INNER];
__device__ __half g_hwout[N_LAYERS * D_MODEL * D_INNER];

// ---------------- helpers ----------------
__device__ __forceinline__ void mma16816(float* c, const uint32_t* a, const uint32_t* b) {
    asm volatile(
        "mma.sync.aligned.m16n8k16.row.col.f32.f16.f16.f32 "
        "{%0,%1,%2,%3}, {%4,%5,%6,%7}, {%8,%9}, {%0,%1,%2,%3};"
        : "+f"(c[0]), "+f"(c[1]), "+f"(c[2]), "+f"(c[3])
        : "r"(a[0]), "r"(a[1]), "r"(a[2]), "r"(a[3]), "r"(b[0]), "r"(b[1]));
}

__device__ __forceinline__ void cp16(uint32_t smem_dst, const void* gsrc) {
    asm volatile("cp.async.cg.shared.global [%0], [%1], 16;" :: "r"(smem_dst), "l"(gsrc));
}

__device__ __forceinline__ void ldsm4(uint32_t* r, uint32_t a) {
    asm volatile("ldmatrix.sync.aligned.m8n8.x4.shared.b16 {%0,%1,%2,%3}, [%4];"
                 : "=r"(r[0]), "=r"(r[1]), "=r"(r[2]), "=r"(r[3]) : "r"(a));
}

// ---------------- fp32 -> fp16 convert (weights) ----------------
__global__ __launch_bounds__(256) void wconv_kernel(
    const float* __restrict__ in, __half* __restrict__ out, int total8)
{
    int t = blockIdx.x * 256 + threadIdx.x;
    if (t >= total8) return;
    const float4* p = (const float4*)in + t * 2;
    float4 a = __ldg(p), b = __ldg(p + 1);
    __half2 h0 = __floats2half2_rn(a.x, a.y);
    __half2 h1 = __floats2half2_rn(a.z, a.w);
    __half2 h2 = __floats2half2_rn(b.x, b.y);
    __half2 h3 = __floats2half2_rn(b.z, b.w);
    uint4 v;
    v.x = *(uint32_t*)&h0; v.y = *(uint32_t*)&h1;
    v.z = *(uint32_t*)&h2; v.w = *(uint32_t*)&h3;
    *((uint4*)(out) + t) = v;
}

// ---------------- residual init copy (kernel, so ncu launch index is stable) ------------
__global__ __launch_bounds__(256) void copy_kernel(const float4* __restrict__ src,
                                                   float4* __restrict__ dst)
{
    int t = blockIdx.x * 256 + threadIdx.x;   // 524288 float4
    dst[t] = __ldg(src + t);
}

// ---------------- layernorm: one warp per row of 512; writes fp16 ----------------
__global__ __launch_bounds__(256) void ln_kernel(
    const float* __restrict__ x, const float* __restrict__ g,
    const float* __restrict__ b, __half* __restrict__ o16)
{
    int warp = (blockIdx.x * blockDim.x + threadIdx.x) >> 5;
    int lane = threadIdx.x & 31;
    const float4* xr = (const float4*)(x + (size_t)warp * D_MODEL);
    float4 v[4];
    float s = 0.f;
    #pragma unroll
    for (int i = 0; i < 4; i++) {
        v[i] = __ldg(xr + lane + 32 * i);
        s += v[i].x + v[i].y + v[i].z + v[i].w;
    }
    #pragma unroll
    for (int o = 16; o; o >>= 1) s += __shfl_xor_sync(0xffffffffu, s, o);
    float mean = s * (1.0f / D_MODEL);
    float vs = 0.f;
    #pragma unroll
    for (int i = 0; i < 4; i++) {
        float dx;
        dx = v[i].x - mean; vs += dx * dx;
        dx = v[i].y - mean; vs += dx * dx;
        dx = v[i].z - mean; vs += dx * dx;
        dx = v[i].w - mean; vs += dx * dx;
    }
    #pragma unroll
    for (int o = 16; o; o >>= 1) vs += __shfl_xor_sync(0xffffffffu, vs, o);
    float inv = rsqrtf(vs * (1.0f / D_MODEL) + 1e-5f);

    const float4* g4 = (const float4*)g;
    const float4* b4 = (const float4*)b;
    __half2* row = (__half2*)(o16 + (size_t)warp * D_MODEL);
    #pragma unroll
    for (int i = 0; i < 4; i++) {
        int idx = lane + 32 * i;
        float4 gv = __ldg(g4 + idx), bv = __ldg(b4 + idx), r;
        r.x = (v[i].x - mean) * inv * gv.x + bv.x;
        r.y = (v[i].y - mean) * inv * gv.y + bv.y;
        r.z = (v[i].z - mean) * inv * gv.z + bv.z;
        r.w = (v[i].w - mean) * inv * gv.w + bv.w;
        row[idx * 2]     = __floats2half2_rn(r.x, r.y);
        row[idx * 2 + 1] = __floats2half2_rn(r.z, r.w);
    }
}

// ---------------- HMMA fp16 GEMM: C[M,N] (+)= A[M,K] * W[N,K]^T --------------------
// BK=64, ldmatrix fragment loads, double-buffered cp.async.
// SMEM row = 64 fp16 + 8 pad = 144B. EPI: 0 = store, 2 = accumulate into C.
template<int BM, int BN, int WM, int WN, int EPI, int NT>
__global__ __launch_bounds__(NT) void hmma_gemm(
    const __half* __restrict__ A, const __half* __restrict__ W,
    float* __restrict__ C, int K, int ldc)
{
    constexpr int BK   = 64;
    constexpr int LDSB = 144;
    constexpr int STAGE = (BM + BN) * LDSB;
    extern __shared__ __align__(16) char sm[];

    const int tid  = threadIdx.x;
    const int wid  = tid >> 5, lane = tid & 31;
    constexpr int WARPS_N = BN / WN;
    const int wm0 = (wid / WARPS_N) * WM;
    const int wn0 = (wid % WARPS_N) * WN;
    const int m0 = blockIdx.y * BM, n0 = blockIdx.x * BN;

    constexpr int MT = WM / 16, NTL = WN / 8;
    float acc[MT][NTL][4];
    #pragma unroll
    for (int i = 0; i < MT; i++)
        #pragma unroll
        for (int j = 0; j < NTL; j++)
            acc[i][j][0] = acc[i][j][1] = acc[i][j][2] = acc[i][j][3] = 0.f;

    constexpr int TOT = (BM + BN) * 8;        // 16B chunks per stage (8 per row)

    auto load_stage = [&](int it, int s) {
        const int k0 = it * BK;
        #pragma unroll
        for (int i = 0; i < TOT / NT; ++i) {
            int ch = tid + i * NT;
            int row = ch >> 3, q = ch & 7;
            const __half* g =
                (row < BM) ? A + (size_t)(m0 + row) * K + k0 + q * 8
                           : W + (size_t)(n0 + row - BM) * K + k0 + q * 8;
            uint32_t d = (uint32_t)__cvta_generic_to_shared(
                sm + s * STAGE + row * LDSB + q * 16);
            cp16(d, g);
        }
    };

    const int ar = lane & 15, ak = (lane >> 4) * 8;          // A: x4 covers 16x16
    const int br = lane & 7,  bg = lane >> 3;                // B: x4 covers two n8xk16

    auto compute = [&](int s) {
        char* abase = sm + s * STAGE;
        char* wbase = abase + BM * LDSB;
        #pragma unroll
        for (int kk = 0; kk < 4; ++kk) {
            uint32_t af[MT][4], bf[NTL][2];
            #pragma unroll
            for (int mt = 0; mt < MT; ++mt) {
                uint32_t a = (uint32_t)__cvta_generic_to_shared(
                    abase + (size_t)(wm0 + mt * 16 + ar) * LDSB + (kk * 16 + ak) * 2);
                ldsm4(af[mt], a);
            }
            #pragma unroll
            for (int np = 0; np < NTL / 2; ++np) {
                int ntsel = np * 2 + (bg >> 1);
                int koff  = (bg & 1) * 8;
                uint32_t a = (uint32_t)__cvta_generic_to_shared(
                    wbase + (size_t)(wn0 + ntsel * 8 + br) * LDSB + (kk * 16 + koff) * 2);
                uint32_t r4[4];
                ldsm4(r4, a);
                bf[np * 2][0] = r4[0]; bf[np * 2][1] = r4[1];
                bf[np * 2 + 1][0] = r4[2]; bf[np * 2 + 1][1] = r4[3];
            }
            #pragma unroll
            for (int mt = 0; mt < MT; ++mt)
                #pragma unroll
                for (int nt = 0; nt < NTL; ++nt)
                    mma16816(acc[mt][nt], af[mt], bf[nt]);
        }
    };

    const int NIT = K / BK;
    load_stage(0, 0);
    asm volatile("cp.async.commit_group;" ::: "memory");

    for (int it = 0; it < NIT; ++it) {
        int s = it & 1;
        if (it + 1 < NIT) {
            load_stage(it + 1, s ^ 1);
            asm volatile("cp.async.commit_group;" ::: "memory");
            asm volatile("cp.async.wait_group 1;" ::: "memory");
        } else {
            asm volatile("cp.async.wait_group 0;" ::: "memory");
        }
        __syncthreads();
        compute(s);
        __syncthreads();
    }

    // epilogue
    const int gr = lane >> 2;
    #pragma unroll
    for (int mt = 0; mt < MT; ++mt) {
        int r = m0 + wm0 + mt * 16 + gr;
        #pragma unroll
        for (int nt = 0; nt < NTL; ++nt) {
            int c = n0 + wn0 + nt * 8 + (lane & 3) * 2;
            float2* p0 = (float2*)&C[(size_t)r * ldc + c];
            float2* p1 = (float2*)&C[(size_t)(r + 8) * ldc + c];
            float2 v0 = make_float2(acc[mt][nt][0], acc[mt][nt][1]);
            float2 v1 = make_float2(acc[mt][nt][2], acc[mt][nt][3]);
            if (EPI == 2) {
                float2 o0 = *p0, o1 = *p1;
                v0.x += o0.x; v0.y += o0.y;
                v1.x += o1.x; v1.y += o1.y;
            }
            *p0 = v0;
            *p1 = v1;
        }
    }
}

// ---------------- SIMT GEMM (kept for dt: K=32, memory bound) ----------------
template<int BM, int BN, int BK, int TM, int TN, int EPI>
__global__ __launch_bounds__(256) void gemm_kernel(
    const float* __restrict__ A, int lda,
    const float* __restrict__ W, int ldb,
    float* __restrict__ C, int ldc,
    int M, int N, int K,
    const float* __restrict__ bias)
{
    __shared__ float As[BK][BM + 4];
    __shared__ float Wt[BK][BN + 4];

    const int tid = threadIdx.x;
    const int m0 = blockIdx.y * BM;
    const int n0 = blockIdx.x * BN;
    constexpr int NTX = BN / TN;
    const int tx = tid % NTX;
    const int ty = tid / NTX;

    float acc[TM][TN];
    #pragma unroll
    for (int i = 0; i < TM; i++)
        #pragma unroll
        for (int j = 0; j < TN; j++) acc[i][j] = 0.f;

    for (int k0 = 0; k0 < K; k0 += BK) {
        for (int i = tid; i < BM * BK; i += 256) {
            int m = i / BK, k = i % BK;
            As[k][m] = __ldg(A + (size_t)(m0 + m) * lda + k0 + k);
        }
        for (int i = tid; i < BN * BK; i += 256) {
            int n = i / BK, k = i % BK;
            Wt[k][n] = __ldg(W + (size_t)(n0 + n) * ldb + k0 + k);
        }
        __syncthreads();
        #pragma unroll
        for (int k = 0; k < BK; ++k) {
            float a[TM], bb[TN];
            #pragma unroll
            for (int i = 0; i < TM; i++) a[i] = As[k][ty * TM + i];
            #pragma unroll
            for (int j = 0; j < TN; j++) bb[j] = Wt[k][tx * TN + j];
            #pragma unroll
            for (int i = 0; i < TM; i++)
                #pragma unroll
                for (int j = 0; j < TN; j++)
                    acc[i][j] = fmaf(a[i], bb[j], acc[i][j]);
        }
        __syncthreads();
    }

    #pragma unroll
    for (int i = 0; i < TM; i++) {
        int m = m0 + ty * TM + i;
        #pragma unroll
        for (int j = 0; j < TN; j++) {
            int n = n0 + tx * TN + j;
            float v = acc[i][j];
            if (EPI == 1) {
                v += __ldg(bias + n);
                v = fmaxf(v, 0.f) + log1pf(expf(-fabsf(v)));
            } else if (EPI == 2) {
                v += C[(size_t)m * ldc + n];
            }
            C[(size_t)m * ldc + n] = v;
        }
    }
}

// ---------------- causal depthwise conv (k=4) + bias + silu; fp32 + fp16 out ----------
__global__ __launch_bounds__(256) void conv_silu_kernel(
    const float* __restrict__ xz, const float* __restrict__ cw,
    const float* __restrict__ cb, float* __restrict__ xc,
    __half* __restrict__ h16)
{
    int idx = blockIdx.x * blockDim.x + threadIdx.x;
    int d  = idx & (D_INNER - 1);
    int tk = idx >> 10;
    int l  = tk & (SEQ - 1);
    int b  = tk >> 10;

    float4 w = __ldg((const float4*)cw + d);
    float acc = __ldg(cb + d);
    const float* base = xz + ((size_t)(b << 10)) * (2 * D_INNER) + d;
    #pragma unroll
    for (int k = 0; k < D_CONV; k++) {
        int lk = l - (D_CONV - 1) + k;
        if (lk >= 0) {
            float xv = __ldg(base + (size_t)lk * (2 * D_INNER));
            float wk = (k == 0) ? w.x : (k == 1) ? w.y : (k == 2) ? w.z : w.w;
            acc = fmaf(wk, xv, acc);
        }
    }
    float sg = 1.f / (1.f + __expf(-acc));
    float val = acc * sg;
    xc[idx] = val;
    h16[idx] = __float2half(val);
}

// ---------------- selective scan; writes fp16 gated y -----------------
__global__ __launch_bounds__(64) void scan_kernel(
    const float* __restrict__ dt, const float* __restrict__ dbl,
    const float* __restrict__ xc, const float* __restrict__ xz,
    const float* __restrict__ A_log, const float* __restrict__ Dp,
    __half* __restrict__ hy)
{
    int tid = blockIdx.x * blockDim.x + threadIdx.x;   // 16384 threads
    int sub = tid & 3;
    int ch  = tid >> 2;
    int d   = ch & (D_INNER - 1);
    int b   = ch >> 10;

    float A0 = -__expf(__ldg(A_log + d * D_STATE + sub * 4 + 0));
    float A1 = -__expf(__ldg(A_log + d * D_STATE + sub * 4 + 1));
    float A2 = -__expf(__ldg(A_log + d * D_STATE + sub * 4 + 2));
    float A3 = -__expf(__ldg(A_log + d * D_STATE + sub * 4 + 3));
    float Dv = __ldg(Dp + d);

    float h0 = 0.f, h1 = 0.f, h2 = 0.f, h3 = 0.f;

    const size_t tk0 = (size_t)(b << 10);
    const float* dtp = dt  + tk0 * D_INNER + d;
    const float* xcp = xc  + tk0 * D_INNER + d;
    const float* zp  = xz  + tk0 * (2 * D_INNER) + D_INNER + d;
    const float* blp = dbl + tk0 * 64 + DT_RANK + sub * 4;
    __half* yp = hy + tk0 * D_INNER + d;

    const int PF = 4;
    float  dtb[PF], xvb[PF], zvb[PF];
    float4 Bb[PF], Cb[PF];
    #pragma unroll
    for (int i = 0; i < PF; i++) {
        dtb[i] = __ldg(dtp + (size_t)i * D_INNER);
        xvb[i] = __ldg(xcp + (size_t)i * D_INNER);
        zvb[i] = __ldg(zp  + (size_t)i * (2 * D_INNER));
        Bb[i]  = *(const float4*)(blp + (size_t)i * 64);
        Cb[i]  = *(const float4*)(blp + (size_t)i * 64 + D_STATE);
    }

    #pragma unroll 4
    for (int l = 0; l < SEQ; ++l) {
        int s = l & (PF - 1);
        float  dtv = dtb[s], xv = xvb[s], zv = zvb[s];
        float4 Bv = Bb[s], Cv = Cb[s];
        int lp = l + PF;
        if (lp < SEQ) {
            dtb[s] = __ldg(dtp + (size_t)lp * D_INNER);
            xvb[s] = __ldg(xcp + (size_t)lp * D_INNER);
            zvb[s] = __ldg(zp  + (size_t)lp * (2 * D_INNER));
            Bb[s]  = *(const float4*)(blp + (size_t)lp * 64);
            Cb[s]  = *(const float4*)(blp + (size_t)lp * 64 + D_STATE);
        }

        float dx = dtv * xv;
        float dA0 = __expf(dtv * A0);
        float dA1 = __expf(dtv * A1);
        float dA2 = __expf(dtv * A2);
        float dA3 = __expf(dtv * A3);
        h0 = fmaf(dA0, h0, dx * Bv.x);
        h1 = fmaf(dA1, h1, dx * Bv.y);
        h2 = fmaf(dA2, h2, dx * Bv.z);
        h3 = fmaf(dA3, h3, dx * Bv.w);
        float yv = h0 * Cv.x;
        yv = fmaf(h1, Cv.y, yv);
        yv = fmaf(h2, Cv.z, yv);
        yv = fmaf(h3, Cv.w, yv);
        yv += __shfl_xor_sync(0xffffffffu, yv, 1);
        yv += __shfl_xor_sync(0xffffffffu, yv, 2);
        if (sub == 0) {
            float yt = fmaf(Dv, xv, yv);
            float sg = 1.f / (1.f + __expf(-zv));
            yp[(size_t)l * D_INNER] = __float2half(yt * (zv * sg));
        }
    }
}

// ---------------- host launcher ----------------
extern "C" void kernel_launch(void* const* d_in, const int* in_sizes, int n_in,
                              void* d_out, int out_size)
{
    const float* x      = (const float*)d_in[0];
    const float* ln_g   = (const float*)d_in[1];
    const float* ln_b   = (const float*)d_in[2];
    const float* in_w   = (const float*)d_in[3];
    const float* conv_w = (const float*)d_in[4];
    const float* conv_b = (const float*)d_in[5];
    const float* xp_w   = (const float*)d_in[6];
    const float* dt_w   = (const float*)d_in[7];
    const float* dt_b   = (const float*)d_in[8];
    const float* A_log  = (const float*)d_in[9];
    const float* Dp     = (const float*)d_in[10];
    const float* out_w  = (const float*)d_in[11];
    float* out = (float*)d_out;

    float *xz, *xc, *dbl, *dtb;
    __half *hxn, *hxc, *hy, *hwin, *hwxp, *hwout;
    cudaGetSymbolAddress((void**)&xz,   g_xz);
    cudaGetSymbolAddress((void**)&xc,   g_xc);
    cudaGetSymbolAddress((void**)&dbl,  g_dbl);
    cudaGetSymbolAddress((void**)&dtb,  g_dt);
    cudaGetSymbolAddress((void**)&hxn,  g_hxn);
    cudaGetSymbolAddress((void**)&hxc,  g_hxc);
    cudaGetSymbolAddress((void**)&hy,   g_hy);
    cudaGetSymbolAddress((void**)&hwin, g_hwin);
    cudaGetSymbolAddress((void**)&hwxp, g_hwxp);
    cudaGetSymbolAddress((void**)&hwout,g_hwout);

    // dynamic smem: 2 stages x (BM+BN) x 144B
    constexpr int SMEM_BIG = 2 * (128 + 128) * 144;   // 73728
    constexpr int SMEM_XP  = 2 * (32 + 64) * 144;     // 27648
    cudaFuncSetAttribute(hmma_gemm<128, 128, 64, 32, 0, 256>,
                         cudaFuncAttributeMaxDynamicSharedMemorySize, SMEM_BIG);
    cudaFuncSetAttribute(hmma_gemm<128, 128, 64, 32, 2, 256>,
                         cudaFuncAttributeMaxDynamicSharedMemorySize, SMEM_BIG);

    // weight converts (all layers)               launches #1..#3
    wconv_kernel<<<2048, 256>>>(in_w,  hwin,  (N_LAYERS * 2 * D_INNER * D_MODEL) / 8);
    wconv_kernel<<<128,  256>>>(xp_w,  hwxp,  (N_LAYERS * 64 * D_INNER) / 8);
    wconv_kernel<<<1024, 256>>>(out_w, hwout, (N_LAYERS * D_MODEL * D_INNER) / 8);

    // residual stream lives in d_out             launch #4
    copy_kernel<<<(M_TOK * D_MODEL / 4) / 256, 256>>>((const float4*)x, (float4*)out);

    for (int i = 0; i < N_LAYERS; ++i) {
        // 1) layernorm -> fp16 hxn               launch #5 (layer 0)
        ln_kernel<<<M_TOK / 8, 256>>>(out, ln_g + (size_t)i * D_MODEL,
                                      ln_b + (size_t)i * D_MODEL, hxn);

        // 2) in_proj (HMMA fp16): xz[4096,2048], K=512   launch #6 -> profiled
        hmma_gemm<128, 128, 64, 32, 0, 256>
            <<<dim3(2 * D_INNER / 128, M_TOK / 128), 256, SMEM_BIG>>>(
            hxn, hwin + (size_t)i * 2 * D_INNER * D_MODEL, xz, D_MODEL, 2 * D_INNER);

        // 3) conv + silu -> xc fp32 + fp16 hxc
        conv_silu_kernel<<<(M_TOK * D_INNER) / 256, 256>>>(
            xz, conv_w + (size_t)i * D_INNER * D_CONV,
            conv_b + (size_t)i * D_INNER, xc, hxc);

        // 4) x_proj (HMMA fp16): dbl[4096,64], K=1024, 128 CTAs
        hmma_gemm<32, 64, 16, 32, 0, 128>
            <<<dim3(1, M_TOK / 32), 128, SMEM_XP>>>(
            hxc, hwxp + (size_t)i * 64 * D_INNER, dbl, D_INNER, 64);

        // 5) dt: softplus(dtr @ dt_w^T + dt_b)  (SIMT — K=32, memory bound)
        gemm_kernel<128, 64, 16, 8, 4, 1><<<dim3(D_INNER / 64, M_TOK / 128), 256>>>(
            dbl, 64, dt_w + (size_t)i * D_INNER * DT_RANK, DT_RANK,
            dtb, D_INNER, M_TOK, D_INNER, DT_RANK, dt_b + (size_t)i * D_INNER);

        // 6) selective scan -> fp16 hy (fused D-skip + silu(z) gate)
        scan_kernel<<<(M_TOK * 4) / 64, 64>>>(
            dtb, dbl, xc, xz, A_log + (size_t)i * D_INNER * D_STATE,
            Dp + (size_t)i * D_INNER, hy);

        // 7) out_proj (HMMA fp16) with residual accumulate, K=1024
        hmma_gemm<128, 128, 64, 32, 2, 256>
            <<<dim3(D_MODEL / 128, M_TOK / 128), 256, SMEM_BIG>>>(
            hy, hwout + (size_t)i * D_MODEL * D_INNER, out, D_INNER, D_MODEL);
    }
    (void)in_sizes; (void)n_in; (void)out_size;
}